// round 3
// baseline (speedup 1.0000x reference)
#include <cuda_runtime.h>
#include <math.h>

#define EPSV 1e-5f
typedef unsigned long long ull;

// ---------------- f32x2 helpers ---------------------------------------------
static __device__ __forceinline__ ull pk2(float lo, float hi) {
    ull r; asm("mov.b64 %0,{%1,%2};" : "=l"(r) : "f"(lo), "f"(hi)); return r;
}
static __device__ __forceinline__ void upk2(ull v, float& lo, float& hi) {
    asm("mov.b64 {%0,%1},%2;" : "=f"(lo), "=f"(hi) : "l"(v));
}
static __device__ __forceinline__ ull f2fma(ull a, ull b, ull c) {
    ull r; asm("fma.rn.f32x2 %0,%1,%2,%3;" : "=l"(r) : "l"(a), "l"(b), "l"(c)); return r;
}
static __device__ __forceinline__ ull f2add(ull a, ull b) {
    ull r; asm("add.rn.f32x2 %0,%1,%2;" : "=l"(r) : "l"(a), "l"(b)); return r;
}

// ---------------- scratch (device globals; no allocation allowed) -----------
__device__ float g_xt[1 * 16 * 16 * 1024];        // (C,H,W,B)
__device__ float g_h1[16 * 14 * 14 * 1024];       // LC1 out (post-BN after bn pass)
__device__ float g_h2[32 * 12 * 12 * 1024];
__device__ float g_h3[64 * 10 * 10 * 1024];       // pre-BN LC3 out (BN3 fused in FC)
__device__ float g_stats[224];                    // sum/sumsq: L1@0, L2@32, L3@96
__device__ float g_part[25 * 10 * 1024];          // FC partials

// ---------------- zero stats each call (graph replays) ----------------------
__global__ void zero_stats_kernel() {
    int i = threadIdx.x;
    if (i < 224) g_stats[i] = 0.f;
}

// ---------------- transpose x: (B,256) -> (256,B) ----------------------------
__global__ void transpose_kernel(const float* __restrict__ x) {
    __shared__ float tile[32][33];
    int p = blockIdx.x * 32 + threadIdx.x;
    int b = blockIdx.y * 32 + threadIdx.y;
    tile[threadIdx.y][threadIdx.x] = x[b * 256 + p];
    __syncthreads();
    int p2 = blockIdx.x * 32 + threadIdx.y;
    int b2 = blockIdx.y * 32 + threadIdx.x;
    g_xt[p2 * 1024 + b2] = tile[threadIdx.x][threadIdx.y];
}

// ---------------- locally-connected layer, f32x2, FMA-bound mainloop --------
// in : (C, HIN, HIN, 1024) clean (post-BN) activations
// W  : (O_TOT, C, OH, OH, 3, 3);  out: (O_TOT, OH, OH, 1024) pre-BN
// block (32, O_BLK/8); grid (OH*OH, 8, O_TOT/O_BLK). Warp: 128 batch, 8 outputs.
template <int C, int HIN, int OH, int O_BLK>
__global__ void __launch_bounds__(32 * (O_BLK / 8))
lc_kernel(const float* __restrict__ in, const float* __restrict__ W,
          const float* __restrict__ bias, float* __restrict__ out,
          float* __restrict__ stats_out) {
    constexpr int KK  = C * 9;
    constexpr int OGR = O_BLK / 8;
    constexpr int NTH = OGR * 32;

    const int loc    = blockIdx.x;
    const int y      = loc / OH;
    const int x      = loc % OH;
    const int o_base = blockIdx.z * O_BLK;
    const int lane   = threadIdx.x;
    const int b0     = blockIdx.y * 128 + lane * 2;
    const int tid    = threadIdx.y * 32 + lane;

    __shared__ __align__(16) float Ws[KK * O_BLK];   // [k][o] k-major
    __shared__ float sbias[O_BLK];

    for (int idx = tid; idx < O_BLK * KK; idx += NTH) {
        int o = idx % O_BLK, k = idx / O_BLK;
        int c = k / 9, ij = k % 9;
        Ws[idx] = W[((((o_base + o) * C + c) * OH + y) * OH + x) * 9 + ij];
    }
    for (int o = tid; o < O_BLK; o += NTH)
        sbias[o] = bias[(o_base + o) * OH * OH + loc];
    __syncthreads();

    ull acc[8][2];
#pragma unroll
    for (int o = 0; o < 8; o++) { acc[o][0] = 0ull; acc[o][1] = 0ull; }

    const int ow = threadIdx.y * 8;
    const float* cp = in + (y * HIN + x) * 1024 + b0;

    for (int c = 0; c < C; c++) {
#pragma unroll
        for (int ij = 0; ij < 9; ij++) {
            const int i = ij / 3, j = ij % 3;
            const float* bp = cp + (i * HIN + j) * 1024;  // compile-time offset
            ull v0 = *(const ull*)bp;
            ull v1 = *(const ull*)(bp + 64);
            const int k = c * 9 + ij;
            float4 wa = *(const float4*)&Ws[k * O_BLK + ow];
            float4 wb = *(const float4*)&Ws[k * O_BLK + ow + 4];
            ull w2[8];
            w2[0] = pk2(wa.x, wa.x); w2[1] = pk2(wa.y, wa.y);
            w2[2] = pk2(wa.z, wa.z); w2[3] = pk2(wa.w, wa.w);
            w2[4] = pk2(wb.x, wb.x); w2[5] = pk2(wb.y, wb.y);
            w2[6] = pk2(wb.z, wb.z); w2[7] = pk2(wb.w, wb.w);
#pragma unroll
            for (int o = 0; o < 8; o++) {
                acc[o][0] = f2fma(v0, w2[o], acc[o][0]);
                acc[o][1] = f2fma(v1, w2[o], acc[o][1]);
            }
        }
        cp += HIN * HIN * 1024;
    }

    // bias + store pre-BN + per-channel BN stats
#pragma unroll
    for (int o = 0; o < 8; o++) {
        int og = o_base + ow + o;
        float bb = sbias[ow + o];
        ull b2 = pk2(bb, bb);
        float* op = out + ((size_t)og * OH * OH + loc) * 1024 + b0;
        ull r0 = f2add(acc[o][0], b2);
        ull r1 = f2add(acc[o][1], b2);
        *(ull*)op = r0;
        *(ull*)(op + 64) = r1;
        ull s2 = f2add(r0, r1);
        ull q2 = f2fma(r1, r1, f2fma(r0, r0, 0ull));
        float sl, sh, ql, qh;
        upk2(s2, sl, sh); upk2(q2, ql, qh);
        float s = sl + sh, q = ql + qh;
#pragma unroll
        for (int off = 16; off > 0; off >>= 1) {
            s += __shfl_down_sync(0xffffffffu, s, off);
            q += __shfl_down_sync(0xffffffffu, q, off);
        }
        if (lane == 0) {
            atomicAdd(&stats_out[og * 2 + 0], s);
            atomicAdd(&stats_out[og * 2 + 1], q);
        }
    }
}

// ---------------- BN apply + ReLU, in place, float4 --------------------------
// grid (per_chan/1024, C), block 256
__global__ void bn_relu_kernel(const float* __restrict__ stats, const float* __restrict__ g,
                               const float* __restrict__ be, float* __restrict__ data,
                               int per_chan, float inv_n) {
    int ch = blockIdx.y;
    float m  = stats[ch * 2 + 0] * inv_n;
    float v  = stats[ch * 2 + 1] * inv_n - m * m;
    float sc = g[ch] * rsqrtf(v + EPSV);
    float sh = be[ch] - sc * m;
    float4* p = (float4*)(data + (size_t)ch * per_chan);
    int i = blockIdx.x * blockDim.x + threadIdx.x;
    float4 t = p[i];
    t.x = fmaxf(fmaf(t.x, sc, sh), 0.f);
    t.y = fmaxf(fmaf(t.y, sc, sh), 0.f);
    t.z = fmaxf(fmaf(t.z, sc, sh), 0.f);
    t.w = fmaxf(fmaf(t.w, sc, sh), 0.f);
    p[i] = t;
}

// ---------------- FC with fused BN3 + tanh -----------------------------------
// h3 pre-BN (64,100,1024); feature f = ch*100+loc. grid (8, 25), block 128.
__global__ void fc_partial_kernel(const float* __restrict__ h, const float* __restrict__ Wfc,
                                  const float* __restrict__ stats, const float* __restrict__ g,
                                  const float* __restrict__ be, float inv_n) {
    const int FCH = 256;
    int b  = blockIdx.x * 128 + threadIdx.x;
    int f0 = blockIdx.y * FCH;
    __shared__ float Wsm[10 * FCH];
    __shared__ float fsc[FCH], fsh[FCH];
    for (int i = threadIdx.x; i < 10 * FCH; i += 128) {
        int t = i / FCH, f = i % FCH;
        Wsm[i] = Wfc[t * 6400 + f0 + f];
    }
    for (int f = threadIdx.x; f < FCH; f += 128) {
        int ch = (f0 + f) / 100;
        float m  = stats[ch * 2 + 0] * inv_n;
        float v  = stats[ch * 2 + 1] * inv_n - m * m;
        float sc = g[ch] * rsqrtf(v + EPSV);
        fsc[f] = sc;
        fsh[f] = be[ch] - sc * m;
    }
    __syncthreads();
    float acc[10];
#pragma unroll
    for (int t = 0; t < 10; t++) acc[t] = 0.f;
    for (int f = 0; f < FCH; f++) {
        float v = h[(size_t)(f0 + f) * 1024 + b];
        v = tanhf(fmaf(v, fsc[f], fsh[f]));
#pragma unroll
        for (int t = 0; t < 10; t++) acc[t] = fmaf(v, Wsm[t * FCH + f], acc[t]);
    }
#pragma unroll
    for (int t = 0; t < 10; t++)
        g_part[((size_t)blockIdx.y * 10 + t) * 1024 + b] = acc[t];
}

__global__ void fc_reduce_kernel(const float* __restrict__ fcb, float* __restrict__ out) {
    int idx = blockIdx.x * blockDim.x + threadIdx.x;
    if (idx >= 10240) return;
    int b = idx / 10, t = idx % 10;
    float s = fcb[t];
#pragma unroll
    for (int c = 0; c < 25; c++) s += g_part[((size_t)c * 10 + t) * 1024 + b];
    out[b * 10 + t] = s;
}

// ---------------- launch -----------------------------------------------------
extern "C" void kernel_launch(void* const* d_in, const int* in_sizes, int n_in,
                              void* d_out, int out_size) {
    const float* x   = (const float*)d_in[0];
    const float* W1  = (const float*)d_in[1];
    const float* b1  = (const float*)d_in[2];
    const float* g1  = (const float*)d_in[3];
    const float* be1 = (const float*)d_in[4];
    const float* W2  = (const float*)d_in[5];
    const float* b2  = (const float*)d_in[6];
    const float* g2  = (const float*)d_in[7];
    const float* be2 = (const float*)d_in[8];
    const float* W3  = (const float*)d_in[9];
    const float* b3  = (const float*)d_in[10];
    const float* g3  = (const float*)d_in[11];
    const float* be3 = (const float*)d_in[12];
    const float* fcW = (const float*)d_in[13];
    const float* fcb = (const float*)d_in[14];
    float* out = (float*)d_out;

    float *p_xt, *p_h1, *p_h2, *p_h3, *p_stats;
    cudaGetSymbolAddress((void**)&p_xt, g_xt);
    cudaGetSymbolAddress((void**)&p_h1, g_h1);
    cudaGetSymbolAddress((void**)&p_h2, g_h2);
    cudaGetSymbolAddress((void**)&p_h3, g_h3);
    cudaGetSymbolAddress((void**)&p_stats, g_stats);

    zero_stats_kernel<<<1, 256>>>();
    transpose_kernel<<<dim3(8, 32), dim3(32, 32)>>>(x);

    // LC1: C=1,HIN=16,OH=14, O=16 -> block 64, grid (196,8)
    lc_kernel<1, 16, 14, 16><<<dim3(196, 8, 1), dim3(32, 2)>>>(p_xt, W1, b1, p_h1, p_stats + 0);
    bn_relu_kernel<<<dim3(196, 16), 256>>>(p_stats + 0, g1, be1, p_h1,
                                           14 * 14 * 1024, 1.f / (14.f * 14.f * 1024.f));

    // LC2: C=16,HIN=14,OH=12, O=32 -> block 128, grid (144,8)
    lc_kernel<16, 14, 12, 32><<<dim3(144, 8, 1), dim3(32, 4)>>>(p_h1, W2, b2, p_h2, p_stats + 32);
    bn_relu_kernel<<<dim3(144, 32), 256>>>(p_stats + 32, g2, be2, p_h2,
                                           12 * 12 * 1024, 1.f / (12.f * 12.f * 1024.f));

    // LC3: C=32,HIN=12,OH=10, O=64 -> two 32-channel o-blocks, grid (100,8,2)
    lc_kernel<32, 12, 10, 32><<<dim3(100, 8, 2), dim3(32, 4)>>>(p_h2, W3, b3, p_h3, p_stats + 96);

    // FC: BN3 + tanh fused into loader
    fc_partial_kernel<<<dim3(8, 25), 128>>>(p_h3, fcW, p_stats + 96, g3, be3,
                                            1.f / (10.f * 10.f * 1024.f));
    fc_reduce_kernel<<<40, 256>>>(fcb, out);
}

// round 4
// speedup vs baseline: 1.1369x; 1.1369x over previous
#include <cuda_runtime.h>
#include <math.h>

#define EPSV 1e-5f
typedef unsigned long long ull;

// ---------------- f32x2 helpers ---------------------------------------------
static __device__ __forceinline__ ull pk2(float lo, float hi) {
    ull r; asm("mov.b64 %0,{%1,%2};" : "=l"(r) : "f"(lo), "f"(hi)); return r;
}
static __device__ __forceinline__ void upk2(ull v, float& lo, float& hi) {
    asm("mov.b64 {%0,%1},%2;" : "=f"(lo), "=f"(hi) : "l"(v));
}
static __device__ __forceinline__ ull f2fma(ull a, ull b, ull c) {
    ull r; asm("fma.rn.f32x2 %0,%1,%2,%3;" : "=l"(r) : "l"(a), "l"(b), "l"(c)); return r;
}
static __device__ __forceinline__ ull f2add(ull a, ull b) {
    ull r; asm("add.rn.f32x2 %0,%1,%2;" : "=l"(r) : "l"(a), "l"(b)); return r;
}

// ---------------- scratch ----------------------------------------------------
__device__ float g_xt[1 * 16 * 16 * 1024];
__device__ float g_h1[16 * 14 * 14 * 1024];
__device__ float g_h2[32 * 12 * 12 * 1024];
__device__ float g_h3[64 * 10 * 10 * 1024];       // pre-BN (BN3 fused in FC)
__device__ float g_stats[224];
__device__ float g_part[25 * 10 * 1024];

__global__ void zero_stats_kernel() {
    int i = threadIdx.x;
    if (i < 224) g_stats[i] = 0.f;
}

__global__ void transpose_kernel(const float* __restrict__ x) {
    __shared__ float tile[32][33];
    int p = blockIdx.x * 32 + threadIdx.x;
    int b = blockIdx.y * 32 + threadIdx.y;
    tile[threadIdx.y][threadIdx.x] = x[b * 256 + p];
    __syncthreads();
    int p2 = blockIdx.x * 32 + threadIdx.y;
    int b2 = blockIdx.y * 32 + threadIdx.x;
    g_xt[p2 * 1024 + b2] = tile[threadIdx.x][threadIdx.y];
}

// ---------------- locally-connected layer ------------------------------------
// in (C,HIN,HIN,1024) post-BN; W (O_TOT,C,OH,OH,3,3); out (O_TOT,OH,OH,1024) pre-BN
// Warp: 8 outputs x 128 batch (MB2=2). Block warps = OGR * CSPLIT.
// CSPLIT=2: c-dim halved across warp groups, smem reduction at end.
// grid (OH*OH, 8, O_TOT/O_BLK)
template <int C, int HIN, int OH, int O_BLK, int CSPLIT, int MINB>
__global__ void __launch_bounds__(32 * (O_BLK / 8) * CSPLIT, MINB)
lc_kernel(const float* __restrict__ in, const float* __restrict__ W,
          const float* __restrict__ bias, float* __restrict__ out,
          float* __restrict__ stats_out) {
    constexpr int KK  = C * 9;
    constexpr int OGR = O_BLK / 8;
    constexpr int NTH = OGR * CSPLIT * 32;
    constexpr int CCH = C / CSPLIT;           // channels per warp-group

    const int loc    = blockIdx.x;
    const int y      = loc / OH;
    const int x      = loc % OH;
    const int o_base = blockIdx.z * O_BLK;
    const int lane   = threadIdx.x;
    const int b0     = blockIdx.y * 128 + lane * 2;
    const int tid    = threadIdx.y * 32 + lane;
    const int ogrp   = threadIdx.y % OGR;
    const int wsplit = threadIdx.y / OGR;

    extern __shared__ __align__(16) unsigned char smraw[];
    ull* Ws2 = (ull*)smraw;                   // [o][k] duplicated-packed

    for (int idx = tid; idx < O_BLK * KK; idx += NTH) {
        int ol = idx / KK, k = idx % KK;
        int c = k / 9, ij = k % 9;
        float w = W[((((o_base + ol) * C + c) * OH + y) * OH + x) * 9 + ij];
        Ws2[idx] = pk2(w, w);
    }
    __syncthreads();

    ull acc[8][2];
#pragma unroll
    for (int o = 0; o < 8; o++) { acc[o][0] = 0ull; acc[o][1] = 0ull; }

    const ull* wp = Ws2 + (ogrp * 8) * KK + wsplit * CCH * 9;
    const float* cp = in + ((wsplit * CCH * HIN * HIN) + y * HIN + x) * 1024 + b0;

    for (int c = 0; c < CCH; c++) {
#pragma unroll
        for (int ij = 0; ij < 9; ij++) {
            const int i = ij / 3, j = ij % 3;
            const float* bp = cp + (i * HIN + j) * 1024;
            ull v0 = *(const ull*)bp;
            ull v1 = *(const ull*)(bp + 64);
            const int k = c * 9 + ij;
#pragma unroll
            for (int o = 0; o < 8; o++) {
                ull w2 = wp[o * KK + k];
                acc[o][0] = f2fma(v0, w2, acc[o][0]);
                acc[o][1] = f2fma(v1, w2, acc[o][1]);
            }
        }
        cp += HIN * HIN * 1024;
    }

    // k-split reduction through smem (overlays weight buffer)
    if (CSPLIT == 2) {
        __syncthreads();                       // weight reads done
        ull* red = (ull*)smraw;                // [ogrp][o*2+m][lane]
        ull* slab = red + (ogrp * 16) * 32;
        if (wsplit == 1) {
#pragma unroll
            for (int o = 0; o < 8; o++) {
                slab[(o * 2 + 0) * 32 + lane] = acc[o][0];
                slab[(o * 2 + 1) * 32 + lane] = acc[o][1];
            }
        }
        __syncthreads();
        if (wsplit == 1) return;
#pragma unroll
        for (int o = 0; o < 8; o++) {
            acc[o][0] = f2add(acc[o][0], slab[(o * 2 + 0) * 32 + lane]);
            acc[o][1] = f2add(acc[o][1], slab[(o * 2 + 1) * 32 + lane]);
        }
    }

    // bias + store pre-BN + per-channel BN stats
#pragma unroll
    for (int o = 0; o < 8; o++) {
        int og = o_base + ogrp * 8 + o;
        float bb = __ldg(&bias[og * OH * OH + loc]);
        ull b2 = pk2(bb, bb);
        float* op = out + ((size_t)og * OH * OH + loc) * 1024 + b0;
        ull r0 = f2add(acc[o][0], b2);
        ull r1 = f2add(acc[o][1], b2);
        *(ull*)op = r0;
        *(ull*)(op + 64) = r1;
        ull s2 = f2add(r0, r1);
        ull q2 = f2fma(r1, r1, f2fma(r0, r0, 0ull));
        float sl, sh, ql, qh;
        upk2(s2, sl, sh); upk2(q2, ql, qh);
        float s = sl + sh, q = ql + qh;
#pragma unroll
        for (int off = 16; off > 0; off >>= 1) {
            s += __shfl_down_sync(0xffffffffu, s, off);
            q += __shfl_down_sync(0xffffffffu, q, off);
        }
        if (lane == 0) {
            atomicAdd(&stats_out[og * 2 + 0], s);
            atomicAdd(&stats_out[og * 2 + 1], q);
        }
    }
}

// ---------------- BN apply + ReLU, in place ----------------------------------
__global__ void bn_relu_kernel(const float* __restrict__ stats, const float* __restrict__ g,
                               const float* __restrict__ be, float* __restrict__ data,
                               int per_chan, float inv_n) {
    int ch = blockIdx.y;
    float m  = stats[ch * 2 + 0] * inv_n;
    float v  = stats[ch * 2 + 1] * inv_n - m * m;
    float sc = g[ch] * rsqrtf(v + EPSV);
    float sh = be[ch] - sc * m;
    float4* p = (float4*)(data + (size_t)ch * per_chan);
    int i = blockIdx.x * blockDim.x + threadIdx.x;
    float4 t = p[i];
    t.x = fmaxf(fmaf(t.x, sc, sh), 0.f);
    t.y = fmaxf(fmaf(t.y, sc, sh), 0.f);
    t.z = fmaxf(fmaf(t.z, sc, sh), 0.f);
    t.w = fmaxf(fmaf(t.w, sc, sh), 0.f);
    p[i] = t;
}

// ---------------- FC with fused BN3 + tanh -----------------------------------
__global__ void fc_partial_kernel(const float* __restrict__ h, const float* __restrict__ Wfc,
                                  const float* __restrict__ stats, const float* __restrict__ g,
                                  const float* __restrict__ be, float inv_n) {
    const int FCH = 256;
    int b  = blockIdx.x * 128 + threadIdx.x;
    int f0 = blockIdx.y * FCH;
    __shared__ float Wsm[10 * FCH];
    __shared__ float fsc[FCH], fsh[FCH];
    for (int i = threadIdx.x; i < 10 * FCH; i += 128) {
        int t = i / FCH, f = i % FCH;
        Wsm[i] = Wfc[t * 6400 + f0 + f];
    }
    for (int f = threadIdx.x; f < FCH; f += 128) {
        int ch = (f0 + f) / 100;
        float m  = stats[ch * 2 + 0] * inv_n;
        float v  = stats[ch * 2 + 1] * inv_n - m * m;
        float sc = g[ch] * rsqrtf(v + EPSV);
        fsc[f] = sc;
        fsh[f] = be[ch] - sc * m;
    }
    __syncthreads();
    float acc[10];
#pragma unroll
    for (int t = 0; t < 10; t++) acc[t] = 0.f;
    for (int f = 0; f < FCH; f++) {
        float v = h[(size_t)(f0 + f) * 1024 + b];
        v = tanhf(fmaf(v, fsc[f], fsh[f]));
#pragma unroll
        for (int t = 0; t < 10; t++) acc[t] = fmaf(v, Wsm[t * FCH + f], acc[t]);
    }
#pragma unroll
    for (int t = 0; t < 10; t++)
        g_part[((size_t)blockIdx.y * 10 + t) * 1024 + b] = acc[t];
}

__global__ void fc_reduce_kernel(const float* __restrict__ fcb, float* __restrict__ out) {
    int idx = blockIdx.x * blockDim.x + threadIdx.x;
    if (idx >= 10240) return;
    int b = idx / 10, t = idx % 10;
    float s = fcb[t];
#pragma unroll
    for (int c = 0; c < 25; c++) s += g_part[((size_t)c * 10 + t) * 1024 + b];
    out[b * 10 + t] = s;
}

// ---------------- launch -----------------------------------------------------
extern "C" void kernel_launch(void* const* d_in, const int* in_sizes, int n_in,
                              void* d_out, int out_size) {
    const float* x   = (const float*)d_in[0];
    const float* W1  = (const float*)d_in[1];
    const float* b1  = (const float*)d_in[2];
    const float* g1  = (const float*)d_in[3];
    const float* be1 = (const float*)d_in[4];
    const float* W2  = (const float*)d_in[5];
    const float* b2  = (const float*)d_in[6];
    const float* g2  = (const float*)d_in[7];
    const float* be2 = (const float*)d_in[8];
    const float* W3  = (const float*)d_in[9];
    const float* b3  = (const float*)d_in[10];
    const float* g3  = (const float*)d_in[11];
    const float* be3 = (const float*)d_in[12];
    const float* fcW = (const float*)d_in[13];
    const float* fcb = (const float*)d_in[14];
    float* out = (float*)d_out;

    float *p_xt, *p_h1, *p_h2, *p_h3, *p_stats;
    cudaGetSymbolAddress((void**)&p_xt, g_xt);
    cudaGetSymbolAddress((void**)&p_h1, g_h1);
    cudaGetSymbolAddress((void**)&p_h2, g_h2);
    cudaGetSymbolAddress((void**)&p_h3, g_h3);
    cudaGetSymbolAddress((void**)&p_stats, g_stats);

    // dynamic smem: packed weights (reduction buffer overlays it)
    const int sm1 = 16 * 9 * 8;          // 1.2 KB
    const int sm2 = 32 * 144 * 8;        // 36.9 KB
    const int sm3 = 32 * 288 * 8;        // 73.7 KB
    cudaFuncSetAttribute((const void*)lc_kernel<1, 16, 14, 16, 1, 10>,
                         cudaFuncAttributeMaxDynamicSharedMemorySize, sm1);
    cudaFuncSetAttribute((const void*)lc_kernel<16, 14, 12, 32, 1, 6>,
                         cudaFuncAttributeMaxDynamicSharedMemorySize, sm2);
    cudaFuncSetAttribute((const void*)lc_kernel<32, 12, 10, 32, 2, 3>,
                         cudaFuncAttributeMaxDynamicSharedMemorySize, sm3);

    zero_stats_kernel<<<1, 256>>>();
    transpose_kernel<<<dim3(8, 32), dim3(32, 32)>>>(x);

    // LC1: C=1 -> O_BLK=16, 2 warps, grid (196,8)
    lc_kernel<1, 16, 14, 16, 1, 10><<<dim3(196, 8, 1), dim3(32, 2), sm1>>>(
        p_xt, W1, b1, p_h1, p_stats + 0);
    bn_relu_kernel<<<dim3(196, 16), 256>>>(p_stats + 0, g1, be1, p_h1,
                                           14 * 14 * 1024, 1.f / (14.f * 14.f * 1024.f));

    // LC2: 4 warps, grid (144,8)
    lc_kernel<16, 14, 12, 32, 1, 6><<<dim3(144, 8, 1), dim3(32, 4), sm2>>>(
        p_h1, W2, b2, p_h2, p_stats + 32);
    bn_relu_kernel<<<dim3(144, 32), 256>>>(p_stats + 32, g2, be2, p_h2,
                                           12 * 12 * 1024, 1.f / (12.f * 12.f * 1024.f));

    // LC3: 8 warps k-split (CSPLIT=2), grid (100,8,2)
    lc_kernel<32, 12, 10, 32, 2, 3><<<dim3(100, 8, 2), dim3(32, 8), sm3>>>(
        p_h2, W3, b3, p_h3, p_stats + 96);

    // FC: BN3 + tanh fused into loader
    fc_partial_kernel<<<dim3(8, 25), 128>>>(p_h3, fcW, p_stats + 96, g3, be3,
                                            1.f / (10.f * 10.f * 1024.f));
    fc_reduce_kernel<<<40, 256>>>(fcb, out);
}

// round 5
// speedup vs baseline: 1.2419x; 1.0923x over previous
#include <cuda_runtime.h>
#include <math.h>

#define EPSV 1e-5f
typedef unsigned long long ull;

// ---------------- f32x2 helpers ---------------------------------------------
static __device__ __forceinline__ ull pk2(float lo, float hi) {
    ull r; asm("mov.b64 %0,{%1,%2};" : "=l"(r) : "f"(lo), "f"(hi)); return r;
}
static __device__ __forceinline__ void upk2(ull v, float& lo, float& hi) {
    asm("mov.b64 {%0,%1},%2;" : "=f"(lo), "=f"(hi) : "l"(v));
}
static __device__ __forceinline__ ull f2fma(ull a, ull b, ull c) {
    ull r; asm("fma.rn.f32x2 %0,%1,%2,%3;" : "=l"(r) : "l"(a), "l"(b), "l"(c)); return r;
}
static __device__ __forceinline__ ull f2add(ull a, ull b) {
    ull r; asm("add.rn.f32x2 %0,%1,%2;" : "=l"(r) : "l"(a), "l"(b)); return r;
}

// ---------------- scratch ----------------------------------------------------
__device__ float g_xt[1 * 16 * 16 * 1024];
__device__ float g_h1[16 * 14 * 14 * 1024];
__device__ float g_h2[32 * 12 * 12 * 1024];
__device__ float g_h3[64 * 10 * 10 * 1024];          // pre-BN (BN3 fused in FC)
__device__ float g_stats[224];
__device__ float g_part[25 * 10 * 1024];
// transposed weights: T[loc][o][k], k = c*9+ij
__device__ float g_w1t[196 * 16 * 9];                // 28224
__device__ float g_w2t[144 * 32 * 144];              // 663552
__device__ float g_w3t[100 * 64 * 288];              // 1843200

// ---------------- fused prep: transpose x + zero stats + weight reorder -----
// grid: [0,256) transpose tiles; 256 = zero stats; [257, ...) weight reorder
__global__ void prep_kernel(const float* __restrict__ x,
                            const float* __restrict__ W1,
                            const float* __restrict__ W2,
                            const float* __restrict__ W3) {
    int bid = blockIdx.x;
    if (bid < 256) {
        __shared__ float tile[32][33];
        int bx = bid % 8, by = bid / 8;
        int tx = threadIdx.x % 32, ty = threadIdx.x / 32;
        // 256 threads = 32x8; loop 4 rows
        for (int r = 0; r < 4; r++) {
            int p = bx * 32 + tx;
            int b = by * 32 + ty + r * 8;
            tile[ty + r * 8][tx] = x[b * 256 + p];
        }
        __syncthreads();
        for (int r = 0; r < 4; r++) {
            int p2 = bx * 32 + ty + r * 8;
            int b2 = by * 32 + tx;
            g_xt[p2 * 1024 + b2] = tile[tx][ty + r * 8];
        }
        return;
    }
    if (bid == 256) {
        if (threadIdx.x < 224) g_stats[threadIdx.x] = 0.f;
        return;
    }
    long idx = (long)(bid - 257) * 256 + threadIdx.x;
    // layer 1: 196*16*9 = 28224
    if (idx < 28224) {
        int k = idx % 9, o = (idx / 9) % 16, loc = idx / (9 * 16);
        g_w1t[idx] = W1[(((o * 1) * 14 + loc / 14) * 14 + loc % 14) * 9 + k];
        return;
    }
    idx -= 28224;
    if (idx < 663552) {   // layer 2: 144 loc * 32 o * 144 k
        int k = idx % 144, o = (idx / 144) % 32, loc = idx / (144 * 32);
        int c = k / 9, ij = k % 9;
        g_w2t[idx] = W2[((((o * 16 + c) * 12 + loc / 12) * 12 + loc % 12)) * 9 + ij];
        return;
    }
    idx -= 663552;
    if (idx < 1843200) {  // layer 3: 100 loc * 64 o * 288 k
        int k = idx % 288, o = (idx / 288) % 64, loc = idx / (288 * 64);
        int c = k / 9, ij = k % 9;
        g_w3t[idx] = W3[((((o * 32 + c) * 10 + loc / 10) * 10 + loc % 10)) * 9 + ij];
    }
}

// ---------------- locally-connected layer, paired-k LDS.128 mainloop --------
// in (C,HIN,HIN,1024) post-BN; WT[loc][o][k]; out (O_TOT,OH,OH,1024) pre-BN
// block (32,2): warp = 8 outputs x 256 batch (MB2=4)
// grid (OH*OH, 4, O_TOT/16)
template <int C, int HIN, int OH, int O_TOT, int MINB>
__global__ void __launch_bounds__(64, MINB)
lc_kernel(const float* __restrict__ in, const float* __restrict__ WT,
          const float* __restrict__ bias, float* __restrict__ out,
          float* __restrict__ stats_out) {
    constexpr int KK  = C * 9;
    constexpr int C10 = C * 10;   // padded k-extent in smem

    const int loc    = blockIdx.x;
    const int o_base = blockIdx.z * 16;
    const int lane   = threadIdx.x;
    const int b0     = blockIdx.y * 256 + lane * 2;
    const int tid    = threadIdx.y * 32 + lane;
    const int ogrp   = threadIdx.y;   // 0..1

    extern __shared__ __align__(16) unsigned char smraw[];
    ull* Ws2 = (ull*)smraw;           // [o (16)][c][10] duplicated-packed

    // coalesced staging from WT
    const float* wsrc = WT + ((size_t)loc * O_TOT + o_base) * KK;
    for (int lin = tid; lin < 16 * KK; lin += 64) {
        int o = lin / KK, k = lin % KK;
        float w = wsrc[lin];
        Ws2[o * C10 + (k / 9) * 10 + (k % 9)] = pk2(w, w);
    }
    __syncthreads();

    ull acc[8][4];
#pragma unroll
    for (int o = 0; o < 8; o++)
#pragma unroll
        for (int m = 0; m < 4; m++) acc[o][m] = 0ull;

    const ull* wp = Ws2 + ogrp * 8 * C10;
    const float* cp = in + ((size_t)(loc / OH) * HIN + (loc % OH)) * 1024 + b0;

    for (int c = 0; c < C; c++) {
#pragma unroll
        for (int p = 0; p < 4; p++) {
            const int ij0 = 2 * p, ij1 = 2 * p + 1;
            const int off0 = ((ij0 / 3) * HIN + (ij0 % 3)) * 1024;
            const int off1 = ((ij1 / 3) * HIN + (ij1 % 3)) * 1024;
            ull v0[4], v1[4];
#pragma unroll
            for (int m = 0; m < 4; m++) v0[m] = *(const ull*)(cp + off0 + 64 * m);
#pragma unroll
            for (int m = 0; m < 4; m++) v1[m] = *(const ull*)(cp + off1 + 64 * m);
#pragma unroll
            for (int o = 0; o < 8; o++) {
                ulonglong2 w = *(const ulonglong2*)&wp[o * C10 + c * 10 + 2 * p];
#pragma unroll
                for (int m = 0; m < 4; m++) acc[o][m] = f2fma(v0[m], w.x, acc[o][m]);
#pragma unroll
                for (int m = 0; m < 4; m++) acc[o][m] = f2fma(v1[m], w.y, acc[o][m]);
            }
        }
        {   // singleton ij = 8 (i=2, j=2)
            const int off = (2 * HIN + 2) * 1024;
            ull v[4];
#pragma unroll
            for (int m = 0; m < 4; m++) v[m] = *(const ull*)(cp + off + 64 * m);
#pragma unroll
            for (int o = 0; o < 8; o++) {
                ull w2 = wp[o * C10 + c * 10 + 8];
#pragma unroll
                for (int m = 0; m < 4; m++) acc[o][m] = f2fma(v[m], w2, acc[o][m]);
            }
        }
        cp += HIN * HIN * 1024;
    }

    // bias + store pre-BN + per-channel BN stats
#pragma unroll
    for (int o = 0; o < 8; o++) {
        int og = o_base + ogrp * 8 + o;
        float bb = __ldg(&bias[og * OH * OH + loc]);
        ull b2 = pk2(bb, bb);
        float* op = out + ((size_t)og * OH * OH + loc) * 1024 + b0;
        ull s2 = 0ull, q2 = 0ull;
#pragma unroll
        for (int m = 0; m < 4; m++) {
            ull r = f2add(acc[o][m], b2);
            *(ull*)(op + 64 * m) = r;
            s2 = f2add(s2, r);
            q2 = f2fma(r, r, q2);
        }
        float sl, sh, ql, qh;
        upk2(s2, sl, sh); upk2(q2, ql, qh);
        float s = sl + sh, q = ql + qh;
#pragma unroll
        for (int off = 16; off > 0; off >>= 1) {
            s += __shfl_down_sync(0xffffffffu, s, off);
            q += __shfl_down_sync(0xffffffffu, q, off);
        }
        if (lane == 0) {
            atomicAdd(&stats_out[og * 2 + 0], s);
            atomicAdd(&stats_out[og * 2 + 1], q);
        }
    }
}

// ---------------- BN apply + ReLU, in place ----------------------------------
__global__ void bn_relu_kernel(const float* __restrict__ stats, const float* __restrict__ g,
                               const float* __restrict__ be, float* __restrict__ data,
                               int per_chan, float inv_n) {
    int ch = blockIdx.y;
    float m  = stats[ch * 2 + 0] * inv_n;
    float v  = stats[ch * 2 + 1] * inv_n - m * m;
    float sc = g[ch] * rsqrtf(v + EPSV);
    float sh = be[ch] - sc * m;
    float4* p = (float4*)(data + (size_t)ch * per_chan);
    int i = blockIdx.x * blockDim.x + threadIdx.x;
    float4 t = p[i];
    t.x = fmaxf(fmaf(t.x, sc, sh), 0.f);
    t.y = fmaxf(fmaf(t.y, sc, sh), 0.f);
    t.z = fmaxf(fmaf(t.z, sc, sh), 0.f);
    t.w = fmaxf(fmaf(t.w, sc, sh), 0.f);
    p[i] = t;
}

// ---------------- FC with fused BN3 + tanh -----------------------------------
__global__ void fc_partial_kernel(const float* __restrict__ h, const float* __restrict__ Wfc,
                                  const float* __restrict__ stats, const float* __restrict__ g,
                                  const float* __restrict__ be, float inv_n) {
    const int FCH = 256;
    int b  = blockIdx.x * 128 + threadIdx.x;
    int f0 = blockIdx.y * FCH;
    __shared__ float Wsm[10 * FCH];
    __shared__ float fsc[FCH], fsh[FCH];
    for (int i = threadIdx.x; i < 10 * FCH; i += 128) {
        int t = i / FCH, f = i % FCH;
        Wsm[i] = Wfc[t * 6400 + f0 + f];
    }
    for (int f = threadIdx.x; f < FCH; f += 128) {
        int ch = (f0 + f) / 100;
        float m  = stats[ch * 2 + 0] * inv_n;
        float v  = stats[ch * 2 + 1] * inv_n - m * m;
        float sc = g[ch] * rsqrtf(v + EPSV);
        fsc[f] = sc;
        fsh[f] = be[ch] - sc * m;
    }
    __syncthreads();
    float acc[10];
#pragma unroll
    for (int t = 0; t < 10; t++) acc[t] = 0.f;
    for (int f = 0; f < FCH; f++) {
        float v = h[(size_t)(f0 + f) * 1024 + b];
        v = tanhf(fmaf(v, fsc[f], fsh[f]));
#pragma unroll
        for (int t = 0; t < 10; t++) acc[t] = fmaf(v, Wsm[t * FCH + f], acc[t]);
    }
#pragma unroll
    for (int t = 0; t < 10; t++)
        g_part[((size_t)blockIdx.y * 10 + t) * 1024 + b] = acc[t];
}

__global__ void fc_reduce_kernel(const float* __restrict__ fcb, float* __restrict__ out) {
    int idx = blockIdx.x * blockDim.x + threadIdx.x;
    if (idx >= 10240) return;
    int b = idx / 10, t = idx % 10;
    float s = fcb[t];
#pragma unroll
    for (int c = 0; c < 25; c++) s += g_part[((size_t)c * 10 + t) * 1024 + b];
    out[b * 10 + t] = s;
}

// ---------------- launch -----------------------------------------------------
extern "C" void kernel_launch(void* const* d_in, const int* in_sizes, int n_in,
                              void* d_out, int out_size) {
    const float* x   = (const float*)d_in[0];
    const float* W1  = (const float*)d_in[1];
    const float* b1  = (const float*)d_in[2];
    const float* g1  = (const float*)d_in[3];
    const float* be1 = (const float*)d_in[4];
    const float* W2  = (const float*)d_in[5];
    const float* b2  = (const float*)d_in[6];
    const float* g2  = (const float*)d_in[7];
    const float* be2 = (const float*)d_in[8];
    const float* W3  = (const float*)d_in[9];
    const float* b3  = (const float*)d_in[10];
    const float* g3  = (const float*)d_in[11];
    const float* be3 = (const float*)d_in[12];
    const float* fcW = (const float*)d_in[13];
    const float* fcb = (const float*)d_in[14];
    float* out = (float*)d_out;

    float *p_xt, *p_h1, *p_h2, *p_h3, *p_stats, *p_w1t, *p_w2t, *p_w3t;
    cudaGetSymbolAddress((void**)&p_xt, g_xt);
    cudaGetSymbolAddress((void**)&p_h1, g_h1);
    cudaGetSymbolAddress((void**)&p_h2, g_h2);
    cudaGetSymbolAddress((void**)&p_h3, g_h3);
    cudaGetSymbolAddress((void**)&p_stats, g_stats);
    cudaGetSymbolAddress((void**)&p_w1t, g_w1t);
    cudaGetSymbolAddress((void**)&p_w2t, g_w2t);
    cudaGetSymbolAddress((void**)&p_w3t, g_w3t);

    // smem: 16 outputs * C*10 padded k-slots * 8B
    const int sm1 = 16 * 1 * 10 * 8;      // 1.28 KB
    const int sm2 = 16 * 16 * 10 * 8;     // 20.5 KB
    const int sm3 = 16 * 32 * 10 * 8;     // 41 KB
    cudaFuncSetAttribute((const void*)lc_kernel<1, 16, 14, 16, 8>,
                         cudaFuncAttributeMaxDynamicSharedMemorySize, sm1);
    cudaFuncSetAttribute((const void*)lc_kernel<16, 14, 12, 32, 8>,
                         cudaFuncAttributeMaxDynamicSharedMemorySize, sm2);
    cudaFuncSetAttribute((const void*)lc_kernel<32, 12, 10, 64, 5>,
                         cudaFuncAttributeMaxDynamicSharedMemorySize, sm3);

    // launch #0: fused prep (transpose + zero stats + weight reorder)
    int wblocks = 257 + (28224 + 663552 + 1843200 + 255) / 256;
    prep_kernel<<<wblocks, 256>>>(x, W1, W2, W3);

    // #1 LC1, #2 bn1, #3 LC2 (profiled slot)
    lc_kernel<1, 16, 14, 16, 8><<<dim3(196, 4, 1), dim3(32, 2), sm1>>>(
        p_xt, p_w1t, b1, p_h1, p_stats + 0);
    bn_relu_kernel<<<dim3(196, 16), 256>>>(p_stats + 0, g1, be1, p_h1,
                                           14 * 14 * 1024, 1.f / (14.f * 14.f * 1024.f));
    lc_kernel<16, 14, 12, 32, 8><<<dim3(144, 4, 2), dim3(32, 2), sm2>>>(
        p_h1, p_w2t, b2, p_h2, p_stats + 32);
    bn_relu_kernel<<<dim3(144, 32), 256>>>(p_stats + 32, g2, be2, p_h2,
                                           12 * 12 * 1024, 1.f / (12.f * 12.f * 1024.f));
    lc_kernel<32, 12, 10, 64, 5><<<dim3(100, 4, 4), dim3(32, 2), sm3>>>(
        p_h2, p_w3t, b3, p_h3, p_stats + 96);

    fc_partial_kernel<<<dim3(8, 25), 128>>>(p_h3, fcW, p_stats + 96, g3, be3,
                                            1.f / (10.f * 10.f * 1024.f));
    fc_reduce_kernel<<<40, 256>>>(fcb, out);
}